// round 1
// baseline (speedup 1.0000x reference)
#include <cuda_runtime.h>

// Packed dual-FMA (sm_100+ PTX). acc holds two partial sums (even/odd d).
#define FMA2(d,a,b,c) asm("fma.rn.f32x2 %0, %1, %2, %3;" : "=l"(d) : "l"(a), "l"(b), "l"(c))

static __device__ float g_c2[1024];
static __device__ int   g_idx[32768];
static __device__ float g_accum[2];   // [0] = sum m*||z-q||^2, [1] = sum m

__global__ void k_init() {
    g_accum[0] = 0.0f;
    g_accum[1] = 0.0f;
}

// ||codebook[k]||^2, one warp per code.
__global__ void k_c2(const float4* __restrict__ cb) {
    int k    = blockIdx.x * 8 + (threadIdx.x >> 5);
    int lane = threadIdx.x & 31;
    float4 a = cb[(size_t)k * 64 + lane];
    float4 b = cb[(size_t)k * 64 + 32 + lane];
    float s = a.x*a.x + a.y*a.y + a.z*a.z + a.w*a.w
            + b.x*b.x + b.y*b.y + b.z*b.z + b.w*b.w;
    #pragma unroll
    for (int o = 16; o; o >>= 1) s += __shfl_down_sync(0xffffffffu, s, o);
    if (lane == 0) g_c2[k] = s;
}

// Main: per 128-token tile, scan all 1024 codes; keep running (min,argmin).
// score[k] = ||c_k||^2 - 2 * <z, c_k>   (argmin-equivalent to full distance)
__global__ __launch_bounds__(256, 1) void k_argmin(const float* __restrict__ z,
                                                   const float* __restrict__ cb) {
    __shared__ float2 zs[128][17];   // tokens x (32 d as 16 float2), pad -> stride 34 words
    __shared__ float2 cs[128][17];   // codes  x (32 d as 16 float2)
    __shared__ float  c2s[128];

    const int tid = threadIdx.x;
    const int tx  = tid & 15;        // code group
    const int ty  = tid >> 4;        // token group
    const int tokBase = blockIdx.x * 128;

    const float2* zg = (const float2*)z;
    const float2* cg = (const float2*)cb;

    float best[8];
    int   bidx[8];
    #pragma unroll
    for (int i = 0; i < 8; i++) { best[i] = 3.0e38f; bidx[i] = 0; }

    for (int kc = 0; kc < 8; kc++) {
        __syncthreads();                       // protect c2s/tiles from prior readers
        if (tid < 128) c2s[tid] = g_c2[kc * 128 + tid];

        unsigned long long acc[8][8];
        #pragma unroll
        for (int i = 0; i < 8; i++)
            #pragma unroll
            for (int j = 0; j < 8; j++) acc[i][j] = 0ull;

        for (int dc = 0; dc < 8; dc++) {
            __syncthreads();
            {   // cooperative tile load: 128 rows x 16 float2, coalesced
                const int col = tid & 15;
                const int r0  = tid >> 4;
                #pragma unroll
                for (int r = 0; r < 8; r++) {
                    int row = r * 16 + r0;
                    zs[row][col] = zg[(size_t)(tokBase + row) * 128 + dc * 16 + col];
                    cs[row][col] = cg[(size_t)(kc * 128 + row) * 128 + dc * 16 + col];
                }
            }
            __syncthreads();
            #pragma unroll 4
            for (int d2 = 0; d2 < 16; d2++) {
                unsigned long long a[8], b[8];
                #pragma unroll
                for (int i = 0; i < 8; i++)
                    a[i] = *(const unsigned long long*)&zs[i * 16 + ty][d2];
                #pragma unroll
                for (int j = 0; j < 8; j++)
                    b[j] = *(const unsigned long long*)&cs[j * 16 + tx][d2];
                #pragma unroll
                for (int i = 0; i < 8; i++)
                    #pragma unroll
                    for (int j = 0; j < 8; j++)
                        FMA2(acc[i][j], a[i], b[j], acc[i][j]);
            }
        }
        // fold this K-chunk into the running argmin (tie -> lower index, jnp semantics)
        #pragma unroll
        for (int i = 0; i < 8; i++) {
            #pragma unroll
            for (int j = 0; j < 8; j++) {
                float2 p  = *(float2*)&acc[i][j];
                float dot = p.x + p.y;
                int  code = kc * 128 + j * 16 + tx;
                float s   = fmaf(-2.0f, dot, c2s[j * 16 + tx]);
                if (s < best[i] || (s == best[i] && code < bidx[i])) {
                    best[i] = s; bidx[i] = code;
                }
            }
        }
    }

    // cross-thread (tx) reduction per token row, reusing tile smem
    __syncthreads();
    float* redS = (float*)zs;
    int*   redI = (int*)cs;
    #pragma unroll
    for (int i = 0; i < 8; i++) {
        int row = i * 16 + ty;
        redS[row * 16 + tx] = best[i];
        redI[row * 16 + tx] = bidx[i];
    }
    __syncthreads();
    if (tid < 128) {
        float bs = redS[tid * 16];
        int   bi = redI[tid * 16];
        #pragma unroll
        for (int t = 1; t < 16; t++) {
            float s = redS[tid * 16 + t];
            int   c = redI[tid * 16 + t];
            if (s < bs || (s == bs && c < bi)) { bs = s; bi = c; }
        }
        g_idx[tokBase + tid] = bi;
    }
}

// One warp per token: gather q=cb[idx], write quantized = (z + (q - z)) * m
// (reference STE rounding), accumulate m*||z-q||^2 and m, write index as float.
__global__ void k_epilogue(const float* __restrict__ z,
                           const float* __restrict__ mask,
                           const float* __restrict__ cb,
                           float* __restrict__ outQ,
                           float* __restrict__ outIdx) {
    __shared__ float sSum[8], sM[8];
    const int warp = threadIdx.x >> 5;
    const int lane = threadIdx.x & 31;
    const int token = blockIdx.x * 8 + warp;

    float m  = mask[token];
    int  idx = g_idx[token];
    const float4* z4 = (const float4*)z  + (size_t)token * 64;
    const float4* q4 = (const float4*)cb + (size_t)idx   * 64;
    float4*       o4 = (float4*)outQ     + (size_t)token * 64;

    float ss = 0.0f;
    #pragma unroll
    for (int r = 0; r < 2; r++) {
        float4 zv = z4[r * 32 + lane];
        float4 qv = q4[r * 32 + lane];
        float dx = zv.x - qv.x, dy = zv.y - qv.y, dz = zv.z - qv.z, dw = zv.w - qv.w;
        ss += dx * dx + dy * dy + dz * dz + dw * dw;
        float4 o;
        o.x = (zv.x + (qv.x - zv.x)) * m;
        o.y = (zv.y + (qv.y - zv.y)) * m;
        o.z = (zv.z + (qv.z - zv.z)) * m;
        o.w = (zv.w + (qv.w - zv.w)) * m;
        o4[r * 32 + lane] = o;
    }
    #pragma unroll
    for (int o = 16; o; o >>= 1) ss += __shfl_down_sync(0xffffffffu, ss, o);
    if (lane == 0) {
        sSum[warp] = ss * m;
        sM[warp]   = m;
        outIdx[token] = (m > 0.0f) ? (float)idx : 0.0f;
    }
    __syncthreads();
    if (threadIdx.x == 0) {
        float a = 0.0f, b = 0.0f;
        #pragma unroll
        for (int w = 0; w < 8; w++) { a += sSum[w]; b += sM[w]; }
        atomicAdd(&g_accum[0], a);
        atomicAdd(&g_accum[1], b);
    }
}

__global__ void k_finalize(float* outLoss) {
    float commitment = g_accum[0] / (g_accum[1] * 256.0f);
    outLoss[0] = 0.25f * commitment;
}

extern "C" void kernel_launch(void* const* d_in, const int* in_sizes, int n_in,
                              void* d_out, int out_size) {
    const float* z    = (const float*)d_in[0];   // (B,S,D) f32
    const float* mask = (const float*)d_in[1];   // (B,S)   f32
    const float* cb   = (const float*)d_in[2];   // (K,D)   f32

    const int BSD = in_sizes[0];   // 8388608
    const int N   = in_sizes[1];   // 32768 tokens

    float* out     = (float*)d_out;
    float* outQ    = out;            // quantized
    float* outLoss = out + BSD;      // scalar vq_loss
    float* outIdx  = out + BSD + 1;  // indices as float

    k_init<<<1, 1>>>();
    k_c2<<<128, 256>>>((const float4*)cb);       // K=1024 codes, 8 warps/block
    k_argmin<<<N / 128, 256>>>(z, cb);
    k_epilogue<<<N / 8, 256>>>(z, mask, cb, outQ, outIdx);
    k_finalize<<<1, 1>>>(outLoss);
}

// round 3
// speedup vs baseline: 1.9690x; 1.9690x over previous
#include <cuda_runtime.h>
#include <cstdint>

// ─────────────── helpers ───────────────
__device__ __forceinline__ uint32_t smem_u32(const void* p) {
    uint32_t a;
    asm("{ .reg .u64 t; cvta.to.shared.u64 t, %1; cvt.u32.u64 %0, t; }"
        : "=r"(a) : "l"(p));
    return a;
}
#define CP_ASYNC16(dst, src) \
    asm volatile("cp.async.cg.shared.global [%0], [%1], 16;" :: "r"(dst), "l"(src) : "memory")
#define CP_COMMIT()  asm volatile("cp.async.commit_group;" ::: "memory")
#define CP_WAIT0()   asm volatile("cp.async.wait_group 0;" ::: "memory")

// baseline tensor-core MMA (sm_80+): D(16x8) += A(16x8,row) * B(8x8,col), tf32
#define MMA_TF32(d, a, b) \
    asm volatile("mma.sync.aligned.m16n8k8.row.col.f32.tf32.tf32.f32 " \
        "{%0,%1,%2,%3}, {%4,%5,%6,%7}, {%8,%9}, {%0,%1,%2,%3};" \
        : "+f"((d)[0]), "+f"((d)[1]), "+f"((d)[2]), "+f"((d)[3]) \
        : "r"((a)[0]), "r"((a)[1]), "r"((a)[2]), "r"((a)[3]), "r"((b)[0]), "r"((b)[1]))

// ─────────────── globals ───────────────
static __device__ float g_c2[1024];
static __device__ int   g_maxcBits;
static __device__ float g_accum[2];           // [0]=sum m*||z-q||^2, [1]=sum m
static __device__ float g_candS[32768 * 8];   // per-token top-8 approx scores (sorted asc)
static __device__ int   g_candI[32768 * 8];

__global__ void k_init() { g_accum[0] = 0.0f; g_accum[1] = 0.0f; g_maxcBits = 0; }

__global__ void k_c2(const float4* __restrict__ cb) {
    int k    = blockIdx.x * 8 + (threadIdx.x >> 5);
    int lane = threadIdx.x & 31;
    float4 a = cb[(size_t)k * 64 + lane];
    float4 b = cb[(size_t)k * 64 + 32 + lane];
    float s = a.x*a.x + a.y*a.y + a.z*a.z + a.w*a.w
            + b.x*b.x + b.y*b.y + b.z*b.z + b.w*b.w;
    #pragma unroll
    for (int o = 16; o; o >>= 1) s += __shfl_down_sync(0xffffffffu, s, o);
    if (lane == 0) {
        g_c2[k] = s;
        atomicMax(&g_maxcBits, __float_as_int(sqrtf(s)));
    }
}

// ─────────────── fused tf32 GEMM + top-8 ───────────────
// CTA: 128 tokens x 1024 codes. 8 N-tiles of 128 codes, K=256 in 8 chunks of 32.
static constexpr int A_STRIDE = 36;                 // floats per row (pad)
static constexpr int A_CHUNK  = 128 * A_STRIDE * 4; // 18432 B
static constexpr int SC_STRIDE = 129;
static constexpr int OFF_A0 = 0;
static constexpr int OFF_A1 = A_CHUNK;
static constexpr int OFF_B0 = 2 * A_CHUNK;
static constexpr int OFF_B1 = 3 * A_CHUNK;
static constexpr int OFF_SC = 4 * A_CHUNK;                      // 73728
static constexpr int DYN_SMEM = OFF_SC + 128 * SC_STRIDE * 4;   // 139776

extern __shared__ char dynsmem[];

__device__ __forceinline__ void fill_chunk(uint32_t sbase, int it, int mtile,
                                           const float* __restrict__ z,
                                           const float* __restrict__ cb, int tid) {
    const int nt = it >> 3, kc = it & 7;
    const uint32_t bufA = sbase + ((it & 1) ? OFF_A1 : OFF_A0);
    const uint32_t bufB = sbase + ((it & 1) ? OFF_B1 : OFF_B0);
    const float* zsrc = z  + (size_t)mtile * 128 * 256 + kc * 32;
    const float* bsrc = cb + (size_t)nt    * 128 * 256 + kc * 32;
    #pragma unroll
    for (int i = 0; i < 4; i++) {
        int u = tid + i * 256, row = u >> 3, q = u & 7;
        CP_ASYNC16(bufA + row * (A_STRIDE * 4) + q * 16, zsrc + (size_t)row * 256 + q * 4);
        CP_ASYNC16(bufB + row * (A_STRIDE * 4) + q * 16, bsrc + (size_t)row * 256 + q * 4);
    }
}

__global__ void __launch_bounds__(256, 1) k_mma(const float* __restrict__ z,
                                                const float* __restrict__ cb) {
    __shared__ float c2sh[128];

    const int tid  = threadIdx.x;
    const int wid  = tid >> 5;
    const int lane = tid & 31;
    const int g    = lane >> 2;     // groupID
    const int tg   = lane & 3;      // thread-in-group
    const int mw   = wid >> 1;      // m-warp 0..3  -> rows [mw*32, mw*32+32)
    const int nw   = wid & 1;       // n-warp 0..1  -> cols [nw*64, nw*64+64)
    const int mtile = blockIdx.x;

    uint32_t sbase = smem_u32(dynsmem);
    const float* As[2] = { (const float*)(dynsmem + OFF_A0), (const float*)(dynsmem + OFF_A1) };
    const float* Bs[2] = { (const float*)(dynsmem + OFF_B0), (const float*)(dynsmem + OFF_B1) };
    float* scoreS = (float*)(dynsmem + OFF_SC);

    // scanner state (threads 0..127 own token = mtile*128 + tid)
    float tb[8]; int ti[8];
    #pragma unroll
    for (int i = 0; i < 8; i++) { tb[i] = 3.0e38f; ti[i] = 0; }

    float acc[2][8][4];

    fill_chunk(sbase, 0, mtile, z, cb, tid);
    CP_COMMIT();

    for (int it = 0; it < 64; it++) {
        const int p  = it & 1;
        const int kc = it & 7;
        const int nt = it >> 3;

        CP_WAIT0();
        __syncthreads();
        if (it + 1 < 64) { fill_chunk(sbase, it + 1, mtile, z, cb, tid); CP_COMMIT(); }

        if (kc == 0) {
            if (tid < 128) c2sh[tid] = g_c2[nt * 128 + tid];
            #pragma unroll
            for (int mt = 0; mt < 2; mt++)
                #pragma unroll
                for (int ntl = 0; ntl < 8; ntl++)
                    #pragma unroll
                    for (int r = 0; r < 4; r++) acc[mt][ntl][r] = 0.0f;
        }

        const uint32_t* A = (const uint32_t*)As[p];
        const uint32_t* B = (const uint32_t*)Bs[p];
        #pragma unroll
        for (int ks = 0; ks < 4; ks++) {
            const int ka = ks * 8;
            uint32_t af[2][4], bf[8][2];
            #pragma unroll
            for (int mt = 0; mt < 2; mt++) {
                int r0 = mw * 32 + mt * 16 + g;
                af[mt][0] = A[r0 * A_STRIDE + ka + tg];
                af[mt][1] = A[(r0 + 8) * A_STRIDE + ka + tg];
                af[mt][2] = A[r0 * A_STRIDE + ka + tg + 4];
                af[mt][3] = A[(r0 + 8) * A_STRIDE + ka + tg + 4];
            }
            #pragma unroll
            for (int ntl = 0; ntl < 8; ntl++) {
                int c0 = nw * 64 + ntl * 8 + g;
                bf[ntl][0] = B[c0 * A_STRIDE + ka + tg];
                bf[ntl][1] = B[c0 * A_STRIDE + ka + tg + 4];
            }
            #pragma unroll
            for (int mt = 0; mt < 2; mt++)
                #pragma unroll
                for (int ntl = 0; ntl < 8; ntl++)
                    MMA_TF32(acc[mt][ntl], af[mt], bf[ntl]);
        }

        if (kc == 7) {
            __syncthreads();   // all warps done with mma for this tile
            #pragma unroll
            for (int mt = 0; mt < 2; mt++) {
                int r0 = mw * 32 + mt * 16 + g;
                #pragma unroll
                for (int ntl = 0; ntl < 8; ntl++) {
                    int c0 = nw * 64 + ntl * 8 + tg * 2;
                    scoreS[r0 * SC_STRIDE + c0]           = acc[mt][ntl][0];
                    scoreS[r0 * SC_STRIDE + c0 + 1]       = acc[mt][ntl][1];
                    scoreS[(r0 + 8) * SC_STRIDE + c0]     = acc[mt][ntl][2];
                    scoreS[(r0 + 8) * SC_STRIDE + c0 + 1] = acc[mt][ntl][3];
                }
            }
            __syncthreads();
            if (tid < 128) {
                const float* row = scoreS + tid * SC_STRIDE;
                #pragma unroll 4
                for (int c = 0; c < 128; c++) {
                    float s = fmaf(-2.0f, row[c], c2sh[c]);
                    if (s < tb[7]) {               // insert (codes scanned ascending -> tie keeps lower)
                        tb[7] = s; ti[7] = nt * 128 + c;
                        #pragma unroll
                        for (int k2 = 7; k2 >= 1; k2--) {
                            if (tb[k2] < tb[k2 - 1]) {
                                float fs = tb[k2]; tb[k2] = tb[k2 - 1]; tb[k2 - 1] = fs;
                                int   is = ti[k2]; ti[k2] = ti[k2 - 1]; ti[k2 - 1] = is;
                            }
                        }
                    }
                }
            }
        }
    }

    if (tid < 128) {
        size_t o = (size_t)(mtile * 128 + tid) * 8;
        #pragma unroll
        for (int i = 0; i < 8; i++) { g_candS[o + i] = tb[i]; g_candI[o + i] = ti[i]; }
    }
}

// ─────────── exact recheck + STE epilogue (1 warp / token) ───────────
__global__ void k_select(const float* __restrict__ z,
                         const float* __restrict__ mask,
                         const float* __restrict__ cb,
                         float* __restrict__ outQ,
                         float* __restrict__ outIdx) {
    __shared__ float zsh[8][256];
    __shared__ float sSum[8], sM[8];
    const int warp = threadIdx.x >> 5;
    const int lane = threadIdx.x & 31;
    const int token = blockIdx.x * 8 + warp;
    const float INF = __int_as_float(0x7f800000);

    float cs = INF; int ci = 0;
    if (lane < 8) {
        cs = g_candS[(size_t)token * 8 + lane];
        ci = g_candI[(size_t)token * 8 + lane];
    }
    const float s0 = __shfl_sync(0xffffffffu, cs, 0);   // best approx
    const float s7 = __shfl_sync(0xffffffffu, cs, 7);   // 8th approx

    const float4* z4 = (const float4*)(z + (size_t)token * 256) + lane * 2;
    float4 za = z4[0], zb = z4[1];
    float zn = za.x*za.x + za.y*za.y + za.z*za.z + za.w*za.w
             + zb.x*zb.x + zb.y*zb.y + zb.z*zb.z + zb.w*zb.w;
    #pragma unroll
    for (int o = 16; o; o >>= 1) zn += __shfl_xor_sync(0xffffffffu, zn, o);

    const float maxc = __int_as_float(g_maxcBits);
    // tf32 truncation: per-score error <= 2^-9 * ||z|| * maxc; add fp32-accum slack
    const float twoDelta = 2.0f * (2.2e-3f * sqrtf(zn) * maxc + 3e-2f);

    float bS; int bI;
    if (s7 > s0 + twoDelta) {
        bS = INF; bI = 0x7fffffff;
        #pragma unroll
        for (int j = 0; j < 8; j++) {
            int idx = __shfl_sync(0xffffffffu, ci, j);
            const float4* c4 = (const float4*)(cb + (size_t)idx * 256) + lane * 2;
            float4 ca = c4[0], cc = c4[1];
            float d = za.x*ca.x + za.y*ca.y + za.z*ca.z + za.w*ca.w
                    + zb.x*cc.x + zb.y*cc.y + zb.z*cc.z + zb.w*cc.w;
            #pragma unroll
            for (int o = 16; o; o >>= 1) d += __shfl_xor_sync(0xffffffffu, d, o);
            float s = fmaf(-2.0f, d, g_c2[idx]);
            if (s < bS || (s == bS && idx < bI)) { bS = s; bI = idx; }
        }
    } else {
        // rare fallback: exact fp32 scan over all 1024 codes
        ((float4*)zsh[warp])[lane * 2] = za;
        ((float4*)zsh[warp])[lane * 2 + 1] = zb;
        __syncwarp();
        bS = INF; bI = 0x7fffffff;
        for (int c = lane; c < 1024; c += 32) {
            float d = 0.0f;
            for (int k = 0; k < 256; k++) d = fmaf(zsh[warp][k], cb[(size_t)c * 256 + k], d);
            float s = fmaf(-2.0f, d, g_c2[c]);
            if (s < bS || (s == bS && c < bI)) { bS = s; bI = c; }
        }
        #pragma unroll
        for (int o = 16; o; o >>= 1) {
            float s2 = __shfl_xor_sync(0xffffffffu, bS, o);
            int   i2 = __shfl_xor_sync(0xffffffffu, bI, o);
            if (s2 < bS || (s2 == bS && i2 < bI)) { bS = s2; bI = i2; }
        }
    }

    const int idx = bI;
    const float m = mask[token];
    const float4* q4 = (const float4*)(cb + (size_t)idx * 256) + lane * 2;
    float4 qa = q4[0], qb = q4[1];

    float ss = 0.0f;
    {
        float dx = za.x - qa.x, dy = za.y - qa.y, dz = za.z - qa.z, dw = za.w - qa.w;
        ss += dx*dx + dy*dy + dz*dz + dw*dw;
        dx = zb.x - qb.x; dy = zb.y - qb.y; dz = zb.z - qb.z; dw = zb.w - qb.w;
        ss += dx*dx + dy*dy + dz*dz + dw*dw;
    }
    float4* o4 = (float4*)(outQ + (size_t)token * 256) + lane * 2;
    float4 oa, ob;
    oa.x = (za.x + (qa.x - za.x)) * m; oa.y = (za.y + (qa.y - za.y)) * m;
    oa.z = (za.z + (qa.z - za.z)) * m; oa.w = (za.w + (qa.w - za.w)) * m;
    ob.x = (zb.x + (qb.x - zb.x)) * m; ob.y = (zb.y + (qb.y - zb.y)) * m;
    ob.z = (zb.z + (qb.z - zb.z)) * m; ob.w = (zb.w + (qb.w - zb.w)) * m;
    o4[0] = oa; o4[1] = ob;

    #pragma unroll
    for (int o = 16; o; o >>= 1) ss += __shfl_down_sync(0xffffffffu, ss, o);
    if (lane == 0) {
        sSum[warp] = ss * m;
        sM[warp]   = m;
        outIdx[token] = (m > 0.0f) ? (float)idx : 0.0f;
    }
    __syncthreads();
    if (threadIdx.x == 0) {
        float a = 0.0f, b = 0.0f;
        #pragma unroll
        for (int w = 0; w < 8; w++) { a += sSum[w]; b += sM[w]; }
        atomicAdd(&g_accum[0], a);
        atomicAdd(&g_accum[1], b);
    }
}

__global__ void k_finalize(float* outLoss) {
    outLoss[0] = 0.25f * (g_accum[0] / (g_accum[1] * 256.0f));
}

// ─────────────── launcher ───────────────
extern "C" void kernel_launch(void* const* d_in, const int* in_sizes, int n_in,
                              void* d_out, int out_size) {
    const float* z    = (const float*)d_in[0];   // (B,S,D)
    const float* mask = (const float*)d_in[1];   // (B,S)
    const float* cb   = (const float*)d_in[2];   // (K,D)

    const int BSD = in_sizes[0];                 // 8388608
    const int N   = in_sizes[1];                 // 32768

    float* out     = (float*)d_out;
    float* outQ    = out;
    float* outLoss = out + BSD;
    float* outIdx  = out + BSD + 1;

    cudaFuncSetAttribute(k_mma, cudaFuncAttributeMaxDynamicSharedMemorySize, DYN_SMEM);

    k_init<<<1, 1>>>();
    k_c2<<<128, 256>>>((const float4*)cb);
    k_mma<<<N / 128, 256, DYN_SMEM>>>(z, cb);
    k_select<<<N / 8, 256>>>(z, mask, cb, outQ, outIdx);
    k_finalize<<<1, 1>>>(outLoss);
}